// round 2
// baseline (speedup 1.0000x reference)
#include <cuda_runtime.h>

#define NUSERS 100000
#define E 64
#define P 128
#define NSHARD 16
#define MSZ 512
#define WD 64
#define RR 4
#define INSZ 256
#define BB 256
#define SS 128
#define IND 384
#define QO 256   // RR*WD

#define STILE 8
#define ROWS 32
#define SCPAD 516
#define MSPAD 68
#define QTPAD 33

__device__ float g_pe[BB * P];
__device__ float g_q[(size_t)BB * SS * QO];
__device__ int g_uid[BB];

// --- normalize user_id (handles int32 or int64 storage) ---
__global__ void k_uid(const int* __restrict__ u) {
    int s = 2;
#pragma unroll
    for (int i = 0; i < 8; i++)
        if (u[2 * i + 1] != 0) s = 1;
    int b = blockIdx.x * blockDim.x + threadIdx.x;
    if (b < BB) g_uid[b] = u[b * s];
}

// --- pe = table[uid] @ W_proc + b_proc ---
__global__ void k_pe(const float* __restrict__ tab, const float* __restrict__ Wp,
                     const float* __restrict__ bp) {
    __shared__ float ue[E];
    int b = blockIdx.x;
    int t = threadIdx.x;  // 128 threads
    int uid = g_uid[b];
    if (t < E) ue[t] = tab[(size_t)uid * E + t];
    __syncthreads();
    float acc = bp[t];
#pragma unroll
    for (int e = 0; e < E; e++) acc += ue[e] * Wp[e * P + t];
    g_pe[b * P + t] = acc;
}

// --- q[b] = concat(x[b], pe[b]) @ Wq[sid(b)]  (per-b GEMM 128x384 @ 384x256) ---
// grid (4 n-tiles, 2 m-tiles, B), 256 threads, 64x64 tile, 4x4 micro-tile
__global__ void k_qgemm(const float* __restrict__ x, const float* __restrict__ Wq) {
    __shared__ float As[64][17];
    __shared__ float Bs[16][64];
    int b = blockIdx.z;
    int n0 = blockIdx.x * 64, m0 = blockIdx.y * 64;
    int sid = ((unsigned)g_uid[b]) % NSHARD;
    const float* Wg = Wq + (size_t)sid * IND * QO;
    int tid = threadIdx.x;
    int tx = tid & 15, ty = tid >> 4;
    float acc[4][4] = {};
    const float* xb = x + ((size_t)b * SS + m0) * INSZ;

    for (int k0 = 0; k0 < IND; k0 += 16) {
        {
            int idx = tid * 4;
            int row = idx >> 4, kk = idx & 15;
            if (k0 < INSZ) {
                float4 v = *(const float4*)&xb[row * INSZ + k0 + kk];
                As[row][kk] = v.x; As[row][kk + 1] = v.y;
                As[row][kk + 2] = v.z; As[row][kk + 3] = v.w;
            } else {
                const float* pe = g_pe + b * P + (k0 - INSZ);
                As[row][kk] = pe[kk]; As[row][kk + 1] = pe[kk + 1];
                As[row][kk + 2] = pe[kk + 2]; As[row][kk + 3] = pe[kk + 3];
            }
        }
        {
            int idx = tid * 4;
            int kk = idx >> 6, nn = idx & 63;
            float4 v = *(const float4*)&Wg[(size_t)(k0 + kk) * QO + n0 + nn];
            *(float4*)&Bs[kk][nn] = v;
        }
        __syncthreads();
#pragma unroll
        for (int kk = 0; kk < 16; kk++) {
            float a[4];
#pragma unroll
            for (int i = 0; i < 4; i++) a[i] = As[ty * 4 + i][kk];
            float4 bv = *(const float4*)&Bs[kk][tx * 4];
            float bb[4] = {bv.x, bv.y, bv.z, bv.w};
#pragma unroll
            for (int i = 0; i < 4; i++)
#pragma unroll
                for (int j = 0; j < 4; j++) acc[i][j] += a[i] * bb[j];
        }
        __syncthreads();
    }
    float* qb = g_q + ((size_t)b * SS + m0) * QO + n0;
#pragma unroll
    for (int i = 0; i < 4; i++) {
        float4 v = {acc[i][0], acc[i][1], acc[i][2], acc[i][3]};
        *(float4*)&qb[(size_t)(ty * 4 + i) * QO + tx * 4] = v;
    }
}

// --- scores -> softmax -> read, fused. block = (b, 8 s-positions) = 32 (s,r) rows ---
// grid (S/STILE, B), 256 threads, dynamic smem ~109KB
__global__ void k_attn(const float* __restrict__ mem, float* __restrict__ out) {
    extern __shared__ float sm[];
    float* qsT = sm;                  // [64][33]   = 2112
    float* sc = sm + 64 * QTPAD;      // [32][516]  = 16512
    float* ms = sc + ROWS * SCPAD;    // [128][68]  = 8704

    int b = blockIdx.y;
    int s0 = blockIdx.x * STILE;
    int tid = threadIdx.x;
    int lane = tid & 31, warp = tid >> 5;
    int sid = ((unsigned)g_uid[b]) % NSHARD;
    const float* M = mem + (size_t)sid * MSZ * WD;

    // stage q transposed: qsT[w][row], row = sl*4 + r (32 rows, 64 w)
    const float* qsrc = g_q + ((size_t)b * SS + s0) * QO;
    for (int i0 = tid * 4; i0 < ROWS * WD; i0 += 1024) {
        float4 v = *(const float4*)&qsrc[i0];
        int row = i0 >> 6;
        int w = i0 & 63;
        qsT[(w + 0) * QTPAD + row] = v.x;
        qsT[(w + 1) * QTPAD + row] = v.y;
        qsT[(w + 2) * QTPAD + row] = v.z;
        qsT[(w + 3) * QTPAD + row] = v.w;
    }

    // ---- phase 1: scores[row][m] = sum_w q[row][w] * mem[m][w] ----
    for (int c = 0; c < 4; c++) {
        __syncthreads();
        for (int i0 = tid * 4; i0 < 128 * 64; i0 += 1024) {
            float4 v = *(const float4*)&M[c * 128 * 64 + i0];
            int m = i0 >> 6, w = i0 & 63;
            *(float4*)&ms[m * MSPAD + w] = v;
        }
        __syncthreads();
        int mBase = warp * 16;
        float acc[16];
#pragma unroll
        for (int i = 0; i < 16; i++) acc[i] = 0.f;
#pragma unroll 2
        for (int k0 = 0; k0 < WD; k0 += 4) {
            float a0 = qsT[(k0 + 0) * QTPAD + lane];
            float a1 = qsT[(k0 + 1) * QTPAD + lane];
            float a2 = qsT[(k0 + 2) * QTPAD + lane];
            float a3 = qsT[(k0 + 3) * QTPAD + lane];
#pragma unroll
            for (int mm = 0; mm < 16; mm++) {
                float4 bv = *(const float4*)&ms[(mBase + mm) * MSPAD + k0];
                acc[mm] += a0 * bv.x + a1 * bv.y + a2 * bv.z + a3 * bv.w;
            }
        }
#pragma unroll
        for (int mm = 0; mm < 16; mm++)
            sc[lane * SCPAD + c * 128 + mBase + mm] = acc[mm];
    }
    __syncthreads();

    // ---- softmax over m (512) per row; warp handles 4 rows ----
    for (int rr = 0; rr < 4; rr++) {
        int row = warp * 4 + rr;
        float* srow = sc + row * SCPAD;
        float vals[16];
        float mx = -1e30f;
#pragma unroll
        for (int j = 0; j < 16; j++) {
            vals[j] = srow[lane + 32 * j];
            mx = fmaxf(mx, vals[j]);
        }
#pragma unroll
        for (int o = 16; o > 0; o >>= 1) mx = fmaxf(mx, __shfl_xor_sync(0xffffffffu, mx, o));
        float sum = 0.f;
#pragma unroll
        for (int j = 0; j < 16; j++) {
            vals[j] = __expf(vals[j] - mx);
            sum += vals[j];
        }
#pragma unroll
        for (int o = 16; o > 0; o >>= 1) sum += __shfl_xor_sync(0xffffffffu, sum, o);
        float inv = 1.f / sum;
#pragma unroll
        for (int j = 0; j < 16; j++) srow[lane + 32 * j] = vals[j] * inv;
        if (b == BB - 1) {
            // final_state = wts of last batch sample: out offset B*S*R*W, layout [S][R][M]
            float* fs = out + (size_t)BB * SS * RR * WD + (size_t)(s0 * 4 + row) * MSZ;
#pragma unroll
            for (int j = 0; j < 16; j++) fs[lane + 32 * j] = vals[j] * inv;
        }
    }

    // ---- phase 2: read[row][w] = sum_m wts[row][m] * mem[m][w] ----
    float acc2[8];
#pragma unroll
    for (int i = 0; i < 8; i++) acc2[i] = 0.f;
    int w0 = warp * 8;
    for (int c = 0; c < 4; c++) {
        __syncthreads();
        for (int i0 = tid * 4; i0 < 128 * 64; i0 += 1024) {
            float4 v = *(const float4*)&M[c * 128 * 64 + i0];
            int m = i0 >> 6, w = i0 & 63;
            *(float4*)&ms[m * MSPAD + w] = v;
        }
        __syncthreads();
#pragma unroll 2
        for (int m0 = 0; m0 < 128; m0 += 4) {
            float4 av = *(const float4*)&sc[lane * SCPAD + c * 128 + m0];
            float aj[4] = {av.x, av.y, av.z, av.w};
#pragma unroll
            for (int j = 0; j < 4; j++) {
                float4 b0 = *(const float4*)&ms[(m0 + j) * MSPAD + w0];
                float4 b1 = *(const float4*)&ms[(m0 + j) * MSPAD + w0 + 4];
                acc2[0] += aj[j] * b0.x; acc2[1] += aj[j] * b0.y;
                acc2[2] += aj[j] * b0.z; acc2[3] += aj[j] * b0.w;
                acc2[4] += aj[j] * b1.x; acc2[5] += aj[j] * b1.y;
                acc2[6] += aj[j] * b1.z; acc2[7] += aj[j] * b1.w;
            }
        }
    }
    // read_words: out[((b*S+s)*R + r)*W + w], row=lane => linear (b*S*4 + s0*4 + row)*64
    float* ob = out + ((size_t)b * SS * 4 + s0 * 4 + lane) * WD + w0;
    float4 v0 = {acc2[0], acc2[1], acc2[2], acc2[3]};
    float4 v1 = {acc2[4], acc2[5], acc2[6], acc2[7]};
    *(float4*)&ob[0] = v0;
    *(float4*)&ob[4] = v1;
}

extern "C" void kernel_launch(void* const* d_in, const int* in_sizes, int n_in,
                              void* d_out, int out_size) {
    const float* x = (const float*)d_in[0];
    const int* uid = (const int*)d_in[1];
    const float* tab = (const float*)d_in[2];
    const float* Wp = (const float*)d_in[3];
    const float* bp = (const float*)d_in[4];
    const float* Wq = (const float*)d_in[5];
    const float* mem = (const float*)d_in[6];
    float* out = (float*)d_out;

    k_uid<<<1, 256>>>(uid);
    k_pe<<<BB, 128>>>(tab, Wp, bp);
    dim3 g2(4, 2, BB);
    k_qgemm<<<g2, 256>>>(x, Wq);

    const int smem_bytes = (64 * QTPAD + ROWS * SCPAD + 128 * MSPAD) * 4;
    cudaFuncSetAttribute(k_attn, cudaFuncAttributeMaxDynamicSharedMemorySize, smem_bytes);
    dim3 g3(SS / STILE, BB);
    k_attn<<<g3, 256, smem_bytes>>>(mem, out);
}

// round 4
// speedup vs baseline: 1.4692x; 1.4692x over previous
#include <cuda_runtime.h>
#include <cstdint>

#define NUSERS 100000
#define E 64
#define P 128
#define NSHARD 16
#define MSZ 512
#define WD 64
#define RR 4
#define INSZ 256
#define BB 256
#define SS 128
#define IND 384
#define QO 256

#define SCP 516
#define MSP 68

__device__ float g_pe[BB * P];
__device__ float g_q[(size_t)BB * SS * QO];
__device__ int g_uid[BB];

// --- normalize user_id (handles int32 or int64 storage) ---
__global__ void k_uid(const int* __restrict__ u) {
    int s = 2;
#pragma unroll
    for (int i = 0; i < 8; i++)
        if (u[2 * i + 1] != 0) s = 1;
    int b = blockIdx.x * blockDim.x + threadIdx.x;
    if (b < BB) g_uid[b] = u[b * s];
}

// --- pe = table[uid] @ W_proc + b_proc ---
__global__ void k_pe(const float* __restrict__ tab, const float* __restrict__ Wp,
                     const float* __restrict__ bp) {
    __shared__ float ue[E];
    int b = blockIdx.x;
    int t = threadIdx.x;
    int uid = g_uid[b];
    if (t < E) ue[t] = tab[(size_t)uid * E + t];
    __syncthreads();
    float acc = bp[t];
#pragma unroll
    for (int e = 0; e < E; e++) acc += ue[e] * Wp[e * P + t];
    g_pe[b * P + t] = acc;
}

// --- q = concat(x, pe) @ Wq[sid]  (scalar tiled GEMM, known-good) ---
__global__ void k_qgemm(const float* __restrict__ x, const float* __restrict__ Wq) {
    __shared__ float As[64][17];
    __shared__ float Bs[16][64];
    int b = blockIdx.z;
    int n0 = blockIdx.x * 64, m0 = blockIdx.y * 64;
    int sid = ((unsigned)g_uid[b]) % NSHARD;
    const float* Wg = Wq + (size_t)sid * IND * QO;
    int tid = threadIdx.x;
    int tx = tid & 15, ty = tid >> 4;
    float acc[4][4] = {};
    const float* xb = x + ((size_t)b * SS + m0) * INSZ;

    for (int k0 = 0; k0 < IND; k0 += 16) {
        {
            int idx = tid * 4;
            int row = idx >> 4, kk = idx & 15;
            if (k0 < INSZ) {
                float4 v = *(const float4*)&xb[row * INSZ + k0 + kk];
                As[row][kk] = v.x; As[row][kk + 1] = v.y;
                As[row][kk + 2] = v.z; As[row][kk + 3] = v.w;
            } else {
                const float* pe = g_pe + b * P + (k0 - INSZ);
                As[row][kk] = pe[kk]; As[row][kk + 1] = pe[kk + 1];
                As[row][kk + 2] = pe[kk + 2]; As[row][kk + 3] = pe[kk + 3];
            }
        }
        {
            int idx = tid * 4;
            int kk = idx >> 6, nn = idx & 63;
            float4 v = *(const float4*)&Wg[(size_t)(k0 + kk) * QO + n0 + nn];
            *(float4*)&Bs[kk][nn] = v;
        }
        __syncthreads();
#pragma unroll
        for (int kk = 0; kk < 16; kk++) {
            float a[4];
#pragma unroll
            for (int i = 0; i < 4; i++) a[i] = As[ty * 4 + i][kk];
            float4 bv = *(const float4*)&Bs[kk][tx * 4];
            float bb[4] = {bv.x, bv.y, bv.z, bv.w};
#pragma unroll
            for (int i = 0; i < 4; i++)
#pragma unroll
                for (int j = 0; j < 4; j++) acc[i][j] += a[i] * bb[j];
        }
        __syncthreads();
    }
    float* qb = g_q + ((size_t)b * SS + m0) * QO + n0;
#pragma unroll
    for (int i = 0; i < 4; i++) {
        float4 v = {acc[i][0], acc[i][1], acc[i][2], acc[i][3]};
        *(float4*)&qb[(size_t)(ty * 4 + i) * QO + tx * 4] = v;
    }
}

// ---------------- mma.sync tf32 helpers ----------------
__device__ __forceinline__ uint32_t t32(float x) {
    uint32_t u;
    asm("cvt.rna.tf32.f32 %0, %1;" : "=r"(u) : "f"(x));
    return u;
}
__device__ __forceinline__ void spl(float x, uint32_t& h, uint32_t& l) {
    h = t32(x);
    l = t32(x - __uint_as_float(h));
}
__device__ __forceinline__ void mma8(float d[4], const uint32_t a[4], uint32_t b0, uint32_t b1) {
    asm volatile(
        "mma.sync.aligned.m16n8k8.row.col.f32.tf32.tf32.f32 "
        "{%0,%1,%2,%3}, {%4,%5,%6,%7}, {%8,%9}, {%0,%1,%2,%3};"
        : "+f"(d[0]), "+f"(d[1]), "+f"(d[2]), "+f"(d[3])
        : "r"(a[0]), "r"(a[1]), "r"(a[2]), "r"(a[3]), "r"(b0), "r"(b1));
}

// ---------------- fused attention via mma.sync tf32 ----------------
// block = (b, 8 s-positions) = 32 (s,r) rows. grid (16, B), 256 threads.
__global__ __launch_bounds__(256, 1) void k_attn(const float* __restrict__ mem,
                                                 float* __restrict__ out) {
    extern __shared__ float sm[];
    float* sc = sm;               // [32][516]
    float* ms = sc + 32 * SCP;    // [128][68]
    float* qs = ms + 128 * MSP;   // [32][68]

    int tid = threadIdx.x;
    int lane = tid & 31, warp = tid >> 5;
    int g = lane >> 2, c = lane & 3;
    int rt = warp >> 2;          // rowtile 0/1 (rows rt*16 .. +15)
    int wq = warp & 3;           // quarter
    int b = blockIdx.y;
    int s0 = blockIdx.x * 8;
    int sid = ((unsigned)g_uid[b]) % NSHARD;
    const float* M = mem + (size_t)sid * MSZ * WD;

    // stage q: qs[row][w], row = s_local*4 + r
    const float* qsrc = g_q + ((size_t)b * SS + s0) * QO;
    for (int i = tid; i < 32 * 16; i += 256) {
        int row = i >> 4, w4 = (i & 15) * 4;
        float4 v = *(const float4*)&qsrc[(size_t)(row >> 2) * QO + (row & 3) * WD + w4];
        *(float4*)&qs[row * MSP + w4] = v;
    }

    uint32_t ah[8][4], al[8][4];

    // ---- phase 1: scores[32,512] = q[32,64] @ mem^T, per 128-m chunk ----
    for (int ch = 0; ch < 4; ch++) {
        for (int i = tid; i < 128 * 16; i += 256) {
            int m = i >> 4, w4 = (i & 15) * 4;
            *(float4*)&ms[m * MSP + w4] = *(const float4*)&M[(size_t)(ch * 128 + m) * WD + w4];
        }
        __syncthreads();
        if (ch == 0) {
#pragma unroll
            for (int k = 0; k < 8; k++) {
                float a0 = qs[(rt * 16 + g) * MSP + k * 8 + c];
                float a1 = qs[(rt * 16 + g + 8) * MSP + k * 8 + c];
                float a2 = qs[(rt * 16 + g) * MSP + k * 8 + c + 4];
                float a3 = qs[(rt * 16 + g + 8) * MSP + k * 8 + c + 4];
                spl(a0, ah[k][0], al[k][0]);
                spl(a1, ah[k][1], al[k][1]);
                spl(a2, ah[k][2], al[k][2]);
                spl(a3, ah[k][3], al[k][3]);
            }
        }
#pragma unroll
        for (int nt = 0; nt < 4; nt++) {
            int n0 = wq * 32 + nt * 8;
            float d[4] = {0.f, 0.f, 0.f, 0.f};
#pragma unroll
            for (int k = 0; k < 8; k++) {
                float b0f = ms[(n0 + g) * MSP + k * 8 + c];
                float b1f = ms[(n0 + g) * MSP + k * 8 + c + 4];
                uint32_t bh0, bl0, bh1, bl1;
                spl(b0f, bh0, bl0);
                spl(b1f, bh1, bl1);
                mma8(d, ah[k], bh0, bh1);
                mma8(d, ah[k], bl0, bl1);
                mma8(d, al[k], bh0, bh1);
            }
            int mg = ch * 128 + n0 + 2 * c;
            float2 v01 = {d[0], d[1]};
            float2 v23 = {d[2], d[3]};
            *(float2*)&sc[(rt * 16 + g) * SCP + mg] = v01;
            *(float2*)&sc[(rt * 16 + g + 8) * SCP + mg] = v23;
        }
        __syncthreads();
    }

    // ---- softmax over m per row; warp handles 4 rows ----
    for (int rr = 0; rr < 4; rr++) {
        int row = warp * 4 + rr;
        float* srow = sc + row * SCP;
        float vals[16];
        float mx = -1e30f;
#pragma unroll
        for (int j = 0; j < 16; j++) {
            vals[j] = srow[lane + 32 * j];
            mx = fmaxf(mx, vals[j]);
        }
#pragma unroll
        for (int o = 16; o > 0; o >>= 1) mx = fmaxf(mx, __shfl_xor_sync(0xffffffffu, mx, o));
        float sum = 0.f;
#pragma unroll
        for (int j = 0; j < 16; j++) {
            vals[j] = __expf(vals[j] - mx);
            sum += vals[j];
        }
#pragma unroll
        for (int o = 16; o > 0; o >>= 1) sum += __shfl_xor_sync(0xffffffffu, sum, o);
        float inv = 1.f / sum;
#pragma unroll
        for (int j = 0; j < 16; j++) srow[lane + 32 * j] = vals[j] * inv;
        if (b == BB - 1) {
            float* fs = out + (size_t)BB * SS * RR * WD + (size_t)(s0 * 4 + row) * MSZ;
#pragma unroll
            for (int j = 0; j < 16; j++) fs[lane + 32 * j] = vals[j] * inv;
        }
    }

    // ---- phase 2: read[32,64] = wts[32,512] @ mem[512,64], accumulate over chunks ----
    float acc[2][4];
#pragma unroll
    for (int nt = 0; nt < 2; nt++)
#pragma unroll
        for (int j = 0; j < 4; j++) acc[nt][j] = 0.f;

    for (int ch = 0; ch < 4; ch++) {
        __syncthreads();
        for (int i = tid; i < 128 * 16; i += 256) {
            int m = i >> 4, w4 = (i & 15) * 4;
            *(float4*)&ms[m * MSP + w4] = *(const float4*)&M[(size_t)(ch * 128 + m) * WD + w4];
        }
        __syncthreads();
#pragma unroll
        for (int kt = 0; kt < 16; kt++) {
            int kg = ch * 128 + kt * 8;
            float a0 = sc[(rt * 16 + g) * SCP + kg + c];
            float a1 = sc[(rt * 16 + g + 8) * SCP + kg + c];
            float a2 = sc[(rt * 16 + g) * SCP + kg + c + 4];
            float a3 = sc[(rt * 16 + g + 8) * SCP + kg + c + 4];
            uint32_t wh[4], wl[4];
            spl(a0, wh[0], wl[0]);
            spl(a1, wh[1], wl[1]);
            spl(a2, wh[2], wl[2]);
            spl(a3, wh[3], wl[3]);
#pragma unroll
            for (int nt = 0; nt < 2; nt++) {
                int n0 = wq * 16 + nt * 8;
                float b0f = ms[(kt * 8 + c) * MSP + n0 + g];
                float b1f = ms[(kt * 8 + c + 4) * MSP + n0 + g];
                uint32_t bh0, bl0, bh1, bl1;
                spl(b0f, bh0, bl0);
                spl(b1f, bh1, bl1);
                mma8(acc[nt], wh, bh0, bh1);
                mma8(acc[nt], wh, bl0, bl1);
                mma8(acc[nt], wl, bh0, bh1);
            }
        }
    }

    // ---- epilogue: write read_words ----
    float* ob = out + ((size_t)b * 512 + s0 * 4) * WD;
#pragma unroll
    for (int nt = 0; nt < 2; nt++) {
        int wcol = wq * 16 + nt * 8 + 2 * c;
        float2 v01 = {acc[nt][0], acc[nt][1]};
        float2 v23 = {acc[nt][2], acc[nt][3]};
        *(float2*)&ob[(size_t)(rt * 16 + g) * WD + wcol] = v01;
        *(float2*)&ob[(size_t)(rt * 16 + g + 8) * WD + wcol] = v23;
    }
}

extern "C" void kernel_launch(void* const* d_in, const int* in_sizes, int n_in,
                              void* d_out, int out_size) {
    const float* x = (const float*)d_in[0];
    const int* uid = (const int*)d_in[1];
    const float* tab = (const float*)d_in[2];
    const float* Wp = (const float*)d_in[3];
    const float* bp = (const float*)d_in[4];
    const float* Wq = (const float*)d_in[5];
    const float* memp = (const float*)d_in[6];
    float* out = (float*)d_out;

    k_uid<<<1, 256>>>(uid);
    k_pe<<<BB, 128>>>(tab, Wp, bp);
    dim3 g2(4, 2, BB);
    k_qgemm<<<g2, 256>>>(x, Wq);

    const int smem_bytes = (32 * SCP + 128 * MSP + 32 * MSP) * 4;
    cudaFuncSetAttribute(k_attn, cudaFuncAttributeMaxDynamicSharedMemorySize, smem_bytes);
    dim3 g3(16, BB);
    k_attn<<<g3, 256, smem_bytes>>>(memp, out);
}